// round 7
// baseline (speedup 1.0000x reference)
#include <cuda_runtime.h>
#include <cstdint>

// Shapes fixed by the reference: B=4, S=2048, K=4096, N=11008, G=128
static constexpr int M_DIM = 8192;   // B*S
static constexpr int K_DIM = 4096;
static constexpr int N_DIM = 11008;

static constexpr int BM = 128;
static constexpr int BN = 128;
static constexpr int BK = 32;
static constexpr int KITERS  = K_DIM / BK;   // 128
static constexpr int TILES_M = M_DIM / BM;   // 64
static constexpr int TILES_N = N_DIM / BN;   // 86
static constexpr int THREADS = 256;

// Padded smem row: 36 floats (144B). Bank(row,col) = (4*row + col) % 32 →
// the 8-rows x 4-cols fragment-load pattern hits all 32 banks conflict-free,
// and 144 % 16 == 0 keeps float4 STS aligned.
static constexpr int LDA = 36;
static constexpr int TILE_FLOATS = BM * LDA;                    // 4608
static constexpr int SMEM_ALLOC  = 2 * 2 * TILE_FLOATS * 4;     // 73728 B

// Round-to-nearest fp32 -> tf32. Explicit RNA avoids the coherent truncation
// bias of the HW's implicit fp32->tf32 conversion inside the MMA.
__device__ __forceinline__ float to_tf32(float x) {
    float r;
    asm("cvt.rna.tf32.f32 %0, %1;" : "=f"(r) : "f"(x));
    return r;
}

__device__ __forceinline__ void mma_tf32(float c[4], const uint32_t a[4], const uint32_t b[2]) {
    asm volatile(
        "mma.sync.aligned.m16n8k8.row.col.f32.tf32.tf32.f32 "
        "{%0,%1,%2,%3}, {%4,%5,%6,%7}, {%8,%9}, {%0,%1,%2,%3};"
        : "+f"(c[0]), "+f"(c[1]), "+f"(c[2]), "+f"(c[3])
        : "r"(a[0]), "r"(a[1]), "r"(a[2]), "r"(a[3]), "r"(b[0]), "r"(b[1]));
}

__global__ void __launch_bounds__(THREADS, 1)
int4gemm_mma(const float* __restrict__ x,
             const int*   __restrict__ qw,
             const float* __restrict__ scales,
             float*       __restrict__ out) {
    extern __shared__ float sm[];
    float* As = sm;                      // [2][BM][LDA]
    float* Bs = sm + 2 * TILE_FLOATS;    // [2][BN][LDA]  (n-major, k contiguous)

    const int tid  = threadIdx.x;
    const int lane = tid & 31;
    const int warp = tid >> 5;
    const int wm   = warp & 1;           // 2 warp-rows of 64
    const int wn   = warp >> 1;          // 4 warp-cols of 32

    // ---- CTA tile mapping with GROUP_M=8 swizzle (L2 reuse of x) ----
    int pid = blockIdx.x;
    const int GM = 8, grp = GM * TILES_N;
    int g = pid / grp, rem = pid - g * grp;
    const int m0 = (g * GM + (rem % GM)) * BM;
    const int n0 = (rem / GM) * BN;

    // ---- A loader: 16 floats/thread as 4x float4 ----
    const int arow = tid >> 3;                 // 0..31 (stride 32 per q)
    const int ac4  = (tid & 7) * 4;            // 0..28
    const float* ap = x + (size_t)(m0 + arow) * K_DIM + ac4;

    // ---- B loader: 2 packed int32/thread (rows j0, j0+2 of the 4-row slab) ----
    const int nl = tid & 127;
    const int j0 = tid >> 7;
    const int*   qp = qw + (size_t)j0 * N_DIM + n0 + nl;
    const float* sp = scales + n0 + nl;

    float acc[4][4][4];
#pragma unroll
    for (int mf = 0; mf < 4; mf++)
#pragma unroll
        for (int nf = 0; nf < 4; nf++)
#pragma unroll
            for (int r = 0; r < 4; r++) acc[mf][nf][r] = 0.0f;

    // Fragment base pointers (conflict-free scalar pattern, see LDA comment)
    const float* Afrag0 = As + (size_t)(wm * 64 + (lane >> 2)) * LDA + (lane & 3);
    const float* Bfrag0 = Bs + (size_t)(wn * 32 + (lane >> 2)) * LDA + (lane & 3);

    float4   a_r[4];
    uint32_t q_r[2];
    float    s_r;

    auto ldg_tile = [&](int it) {
#pragma unroll
        for (int q = 0; q < 4; q++)
            a_r[q] = *(const float4*)(ap + (size_t)q * 32 * K_DIM + (size_t)it * BK);
        const size_t qoff = (size_t)it * 4 * N_DIM;
        q_r[0] = (uint32_t)__ldg(qp + qoff);
        q_r[1] = (uint32_t)__ldg(qp + qoff + 2 * (size_t)N_DIM);
        s_r    = __ldg(sp + (size_t)(it >> 2) * N_DIM);     // group = (it*32)/128
    };

    auto sts_tile = [&](int st) {
        float* ab = As + st * TILE_FLOATS;
        float* bb = Bs + st * TILE_FLOATS;
#pragma unroll
        for (int q = 0; q < 4; q++) {
            float4 v = a_r[q];
            v.x = to_tf32(v.x); v.y = to_tf32(v.y);
            v.z = to_tf32(v.z); v.w = to_tf32(v.w);
            *(float4*)(ab + (size_t)(arow + 32 * q) * LDA + ac4) = v;
        }
#pragma unroll
        for (int i = 0; i < 2; i++) {
            const uint32_t w32 = q_r[i];
            float f[8];
#pragma unroll
            for (int t = 0; t < 8; t++) {
                int nib = (int)((w32 >> (4 * t)) & 15u);    // nibble t -> k offset t
                f[t] = to_tf32((float)(nib - 8) * s_r);
            }
            float* p = bb + (size_t)nl * LDA + 8 * (j0 + 2 * i);
            *(float4*)(p)     = make_float4(f[0], f[1], f[2], f[3]);
            *(float4*)(p + 4) = make_float4(f[4], f[5], f[6], f[7]);
        }
    };

    // ---- Prologue ----
    ldg_tile(0);
    sts_tile(0);
    __syncthreads();

    // ---- Mainloop: double-buffered smem, global prefetch one iter ahead ----
#pragma unroll 1
    for (int it = 0; it < KITERS; ++it) {
        const int st = it & 1;
        const bool has_next = (it + 1) < KITERS;
        if (has_next) ldg_tile(it + 1);

        const float* Af = Afrag0 + st * TILE_FLOATS;
        const float* Bf = Bfrag0 + st * TILE_FLOATS;
#pragma unroll
        for (int kc = 0; kc < BK; kc += 8) {
            uint32_t af[4][4];
#pragma unroll
            for (int mf = 0; mf < 4; mf++) {
                const float* p = Af + (size_t)mf * 16 * LDA + kc;
                af[mf][0] = __float_as_uint(p[0]);             // (row,   k)
                af[mf][1] = __float_as_uint(p[8 * LDA]);       // (row+8, k)
                af[mf][2] = __float_as_uint(p[4]);             // (row,   k+4)
                af[mf][3] = __float_as_uint(p[8 * LDA + 4]);   // (row+8, k+4)
            }
            uint32_t bf[4][2];
#pragma unroll
            for (int nf = 0; nf < 4; nf++) {
                const float* p = Bf + (size_t)nf * 8 * LDA + kc;
                bf[nf][0] = __float_as_uint(p[0]);             // (n, k)
                bf[nf][1] = __float_as_uint(p[4]);             // (n, k+4)
            }
#pragma unroll
            for (int mf = 0; mf < 4; mf++)
#pragma unroll
                for (int nf = 0; nf < 4; nf++)
                    mma_tf32(acc[mf][nf], af[mf], bf[nf]);
        }

        if (has_next) {
            sts_tile(st ^ 1);
            __syncthreads();
        }
    }

    // ---- Epilogue: m16n8 accum layout -> float2 global stores ----
    const int r0 = m0 + wm * 64 + (lane >> 2);
    const int c0 = n0 + wn * 32 + (lane & 3) * 2;   // even -> 8B aligned
#pragma unroll
    for (int mf = 0; mf < 4; mf++) {
#pragma unroll
        for (int nf = 0; nf < 4; nf++) {
            float* p = out + (size_t)(r0 + mf * 16) * N_DIM + c0 + nf * 8;
            *(float2*)p               = make_float2(acc[mf][nf][0], acc[mf][nf][1]);
            *(float2*)(p + 8 * N_DIM) = make_float2(acc[mf][nf][2], acc[mf][nf][3]);
        }
    }
}

extern "C" void kernel_launch(void* const* d_in, const int* in_sizes, int n_in,
                              void* d_out, int out_size) {
    const float* x      = (const float*)d_in[0];
    const int*   qw     = (const int*)d_in[1];
    const float* scales = (const float*)d_in[2];
    // d_in[3] = group_size (always 128; shapes fixed)
    float* out = (float*)d_out;

    cudaFuncSetAttribute(int4gemm_mma,
                         cudaFuncAttributeMaxDynamicSharedMemorySize, SMEM_ALLOC);

    const int grid = TILES_M * TILES_N;   // 5504
    int4gemm_mma<<<grid, THREADS, SMEM_ALLOC>>>(x, qw, scales, out);
}

// round 8
// speedup vs baseline: 1.2471x; 1.2471x over previous
#include <cuda_runtime.h>
#include <cstdint>

// Shapes fixed by the reference: B=4, S=2048, K=4096, N=11008, G=128
static constexpr int M_DIM = 8192;   // B*S
static constexpr int K_DIM = 4096;
static constexpr int N_DIM = 11008;

static constexpr int BM = 128;
static constexpr int BN = 128;
static constexpr int BK = 32;
static constexpr int KITERS  = K_DIM / BK;   // 128
static constexpr int TILES_M = M_DIM / BM;   // 64
static constexpr int TILES_N = N_DIM / BN;   // 86
static constexpr int THREADS = 256;
static constexpr int NSTAGE  = 4;

// Padded A row: 36 floats (144B). Bank(row,col) = (4*row+col)%32 -> the
// 8-rows x 4-cols fragment pattern hits all 32 banks; 144%16==0 keeps the
// 16B cp.async destinations aligned.
static constexpr int LDA = 36;
static constexpr int A_STG_F = BM * LDA;          // 4608 floats
static constexpr int A_STG_B = A_STG_F * 4;       // 18432 B
static constexpr int B_STG_W = 4 * BN;            // 512 packed int32 (raw int4)
static constexpr int B_STG_B = B_STG_W * 4;       // 2048 B
static constexpr int S_STG_B = BN * 4;            // 512 B (group scales)

static constexpr int OFF_A = 0;
static constexpr int OFF_B = NSTAGE * A_STG_B;                 // 73728
static constexpr int OFF_S = OFF_B + NSTAGE * B_STG_B;         // 81920
static constexpr int SMEM_ALLOC = OFF_S + NSTAGE * S_STG_B;    // 83968 B

__device__ __forceinline__ uint32_t smem_u32(const void* p) {
    uint32_t a;
    asm("{ .reg .u64 t; cvta.to.shared.u64 t, %1; cvt.u32.u64 %0, t; }" : "=r"(a) : "l"(p));
    return a;
}
// Round-to-nearest fp32 -> tf32 (B path: avoids coherent truncation bias).
__device__ __forceinline__ float to_tf32(float x) {
    float r;
    asm("cvt.rna.tf32.f32 %0, %1;" : "=f"(r) : "f"(x));
    return r;
}
__device__ __forceinline__ void cp16(uint32_t dst, const void* src) {
    asm volatile("cp.async.cg.shared.global [%0], [%1], 16;" :: "r"(dst), "l"(src));
}
__device__ __forceinline__ void cp_commit() {
    asm volatile("cp.async.commit_group;" ::: "memory");
}
__device__ __forceinline__ void cp_wait2() {
    asm volatile("cp.async.wait_group 2;" ::: "memory");
}

__device__ __forceinline__ void mma_tf32(float c[4], const uint32_t a[4], const uint32_t b[2]) {
    asm volatile(
        "mma.sync.aligned.m16n8k8.row.col.f32.tf32.tf32.f32 "
        "{%0,%1,%2,%3}, {%4,%5,%6,%7}, {%8,%9}, {%0,%1,%2,%3};"
        : "+f"(c[0]), "+f"(c[1]), "+f"(c[2]), "+f"(c[3])
        : "r"(a[0]), "r"(a[1]), "r"(a[2]), "r"(a[3]), "r"(b[0]), "r"(b[1]));
}

__global__ void __launch_bounds__(THREADS, 2)
int4gemm_mma(const float* __restrict__ x,
             const int*   __restrict__ qw,
             const float* __restrict__ scales,
             float*       __restrict__ out) {
    extern __shared__ char sm[];
    const uint32_t sb = smem_u32(sm);

    const int tid  = threadIdx.x;
    const int lane = tid & 31;
    const int warp = tid >> 5;
    const int wm   = warp & 1;           // 2 warp-rows of 64
    const int wn   = warp >> 1;          // 4 warp-cols of 32

    // ---- CTA tile mapping with GROUP_M=8 swizzle (L2 reuse of x) ----
    int pid = blockIdx.x;
    const int GM = 8, grp = GM * TILES_N;
    int g = pid / grp, rem = pid - g * grp;
    const int m0 = (g * GM + (rem % GM)) * BM;
    const int n0 = (rem / GM) * BN;

    // ---- producer addressing ----
    const int arow = tid >> 3;                  // 0..31 (stride 32 per q)
    const int ac4  = (tid & 7) * 4;             // 0..28
    const float* ap = x + (size_t)(m0 + arow) * K_DIM + ac4;
    uint32_t adst[4];
#pragma unroll
    for (int q = 0; q < 4; q++)
        adst[q] = sb + OFF_A + (uint32_t)(((arow + 32 * q) * LDA + ac4) * 4);

    const int* qsrc = qw + (size_t)(tid >> 5) * N_DIM + n0 + (tid & 31) * 4;  // tid<128
    const float* ssrc = scales + n0 + tid * 4;                                // tid<32

    auto issue_copy = [&](int it, int st) {
        const uint32_t abase = (uint32_t)(st * A_STG_B);
#pragma unroll
        for (int q = 0; q < 4; q++)
            cp16(adst[q] + abase, ap + (size_t)q * 32 * K_DIM + (size_t)it * BK);
        if (tid < 128)
            cp16(sb + OFF_B + st * B_STG_B + tid * 16, qsrc + (size_t)(4 * it) * N_DIM);
        if (tid < 32)
            cp16(sb + OFF_S + st * S_STG_B + tid * 16, ssrc + (size_t)(it >> 2) * N_DIM);
    };

    // ---- consumer bases ----
    float*    Asf = (float*)sm;                        // OFF_A == 0
    uint32_t* Bqw = (uint32_t*)(sm + OFF_B);
    float*    Ssf = (float*)(sm + OFF_S);
    const int afbase = (wm * 64 + (lane >> 2)) * LDA + (lane & 3);
    const int bnl    = wn * 32 + (lane >> 2);          // n within tile (per nf add 8*nf)
    const int sh0    = (lane & 3) * 4;                 // nibble shift for k = kc*8 + (lane&3)

    float acc[4][4][4];
#pragma unroll
    for (int mf = 0; mf < 4; mf++)
#pragma unroll
        for (int nf = 0; nf < 4; nf++)
#pragma unroll
            for (int r = 0; r < 4; r++) acc[mf][nf][r] = 0.0f;

    // ---- prologue: fill NSTAGE-1 stages ----
#pragma unroll
    for (int p = 0; p < NSTAGE - 1; p++) { issue_copy(p, p); cp_commit(); }

    // ---- mainloop ----
#pragma unroll 1
    for (int it = 0; it < KITERS; ++it) {
        const int st = it & (NSTAGE - 1);

        cp_wait2();          // stage st complete (this thread's groups)
        __syncthreads();     // ...and everyone else's; also fences stage reuse

        const int nxt = it + NSTAGE - 1;
        if (nxt < KITERS) issue_copy(nxt, nxt & (NSTAGE - 1));
        cp_commit();         // unconditional: keeps group counting uniform

        // per-iter group scales (8 distinct words, 4-way broadcast)
        float s[4], m8[4];
#pragma unroll
        for (int nf = 0; nf < 4; nf++) {
            s[nf]  = Ssf[st * BN + bnl + nf * 8];
            m8[nf] = -8.0f * s[nf];
        }

        const float*    Af = Asf + st * A_STG_F + afbase;
        const uint32_t* Bw = Bqw + st * B_STG_W;

#pragma unroll
        for (int kci = 0; kci < 4; kci++) {
            uint32_t af[4][4];
#pragma unroll
            for (int mf = 0; mf < 4; mf++) {
                const float* p = Af + (size_t)mf * 16 * LDA + kci * 8;
                af[mf][0] = __float_as_uint(p[0]);
                af[mf][1] = __float_as_uint(p[8 * LDA]);
                af[mf][2] = __float_as_uint(p[4]);
                af[mf][3] = __float_as_uint(p[8 * LDA + 4]);
            }
            uint32_t bf[4][2];
#pragma unroll
            for (int nf = 0; nf < 4; nf++) {
                const uint32_t w = Bw[kci * BN + bnl + nf * 8];
                // k = kci*8 + (lane&3) and +4  ->  nibbles sh0 and sh0+16
                float f0 = fmaf((float)((w >> sh0) & 15u),        s[nf], m8[nf]);
                float f1 = fmaf((float)((w >> (sh0 + 16)) & 15u), s[nf], m8[nf]);
                bf[nf][0] = __float_as_uint(to_tf32(f0));
                bf[nf][1] = __float_as_uint(to_tf32(f1));
            }
#pragma unroll
            for (int mf = 0; mf < 4; mf++)
#pragma unroll
                for (int nf = 0; nf < 4; nf++)
                    mma_tf32(acc[mf][nf], af[mf], bf[nf]);
        }
    }

    // ---- epilogue: m16n8 accum layout -> float2 global stores ----
    const int r0 = m0 + wm * 64 + (lane >> 2);
    const int c0 = n0 + wn * 32 + (lane & 3) * 2;   // even -> 8B aligned
#pragma unroll
    for (int mf = 0; mf < 4; mf++) {
#pragma unroll
        for (int nf = 0; nf < 4; nf++) {
            float* p = out + (size_t)(r0 + mf * 16) * N_DIM + c0 + nf * 8;
            *(float2*)p               = make_float2(acc[mf][nf][0], acc[mf][nf][1]);
            *(float2*)(p + 8 * N_DIM) = make_float2(acc[mf][nf][2], acc[mf][nf][3]);
        }
    }
}

extern "C" void kernel_launch(void* const* d_in, const int* in_sizes, int n_in,
                              void* d_out, int out_size) {
    const float* x      = (const float*)d_in[0];
    const int*   qw     = (const int*)d_in[1];
    const float* scales = (const float*)d_in[2];
    // d_in[3] = group_size (always 128; shapes fixed)
    float* out = (float*)d_out;

    cudaFuncSetAttribute(int4gemm_mma,
                         cudaFuncAttributeMaxDynamicSharedMemorySize, SMEM_ALLOC);

    const int grid = TILES_M * TILES_N;   // 5504
    int4gemm_mma<<<grid, THREADS, SMEM_ALLOC>>>(x, qw, scales, out);
}